// round 9
// baseline (speedup 1.0000x reference)
#include <cuda_runtime.h>
#include <math.h>
#include <stdint.h>

// Problem constants (B=2, S=4096 -> N=8192 tokens)
#define NTOK 8192
#define DDIM 2048
#define ENUM 8
#define FDIM 8192

// ---------------------------------------------------------------------------
// Device scratch (no allocations allowed -> __device__ globals)
// ---------------------------------------------------------------------------
__device__ float g_logits[NTOK * ENUM];          // [N, E] router logits
__device__ float g_sums[ENUM];                   // per-expert logit sums
__device__ int   g_sel[2];                       // top-2 expert indices
__device__ float g_rw[NTOK * 2];                 // per-token softmax weights
__device__ float g_h[(size_t)NTOK * 2 * FDIM];   // [N, 2F]: rw-scaled hidden, tf32
__device__ float g_xr[(size_t)NTOK * DDIM];      // x rounded to tf32
__device__ float g_w1r[(size_t)2 * DDIM * FDIM]; // selected w1 slices, tf32
__device__ float g_w2r[(size_t)2 * FDIM * DDIM]; // selected w2 slices, tf32 ([2F, D])

// ---------------------------------------------------------------------------
// Helpers
// ---------------------------------------------------------------------------
__device__ __forceinline__ float to_tf32(float x) {
    uint32_t u;
    asm("cvt.rna.tf32.f32 %0, %1;" : "=r"(u) : "f"(x));
    return __uint_as_float(u);
}

__device__ __forceinline__ float gelu_tanh(float v) {
    const float c0 = 0.7978845608028654f;   // sqrt(2/pi)
    const float c1 = 0.044715f;
    float v3 = v * v * v;
    float t = tanhf(c0 * (v + c1 * v3));
    return 0.5f * v * (1.0f + t);
}

__device__ __forceinline__ void mma_tf32(float (&c)[4], const uint32_t (&a)[4],
                                         const uint32_t (&b)[2]) {
    asm volatile(
        "mma.sync.aligned.m16n8k8.row.col.f32.tf32.tf32.f32 "
        "{%0,%1,%2,%3}, {%4,%5,%6,%7}, {%8,%9}, {%0,%1,%2,%3};"
        : "+f"(c[0]), "+f"(c[1]), "+f"(c[2]), "+f"(c[3])
        : "r"(a[0]), "r"(a[1]), "r"(a[2]), "r"(a[3]), "r"(b[0]), "r"(b[1]));
}

// mbarrier + 1D bulk-copy wrappers (sm_90 baseline features; no 'a' needed)
#define MBINIT(addr, cnt) \
    asm volatile("mbarrier.init.shared.b64 [%0], %1;" :: "r"(addr), "r"(cnt) : "memory")

#define MBEXPECT(addr, bytes) \
    asm volatile("mbarrier.arrive.expect_tx.shared.b64 _, [%0], %1;" \
                 :: "r"(addr), "r"(bytes) : "memory")

#define MBWAIT(addr, parity) do {                                            \
    asm volatile(                                                            \
        "{\n\t.reg .pred P;\n\t"                                             \
        "WL%=:\n\t"                                                          \
        "mbarrier.try_wait.parity.acquire.cta.shared::cta.b64 P, [%0], %1, 0x989680;\n\t" \
        "@P bra WD%=;\n\t"                                                   \
        "bra WL%=;\n\t"                                                      \
        "WD%=:\n\t}"                                                         \
        :: "r"((uint32_t)(addr)), "r"((uint32_t)(parity)) : "memory");       \
} while (0)

#define BULK(dst, src, bytes, mbar)                                          \
    asm volatile("cp.async.bulk.shared::cluster.global.mbarrier::complete_tx::bytes " \
                 "[%0], [%1], %2, [%3];"                                     \
                 :: "r"((uint32_t)(dst)), "l"(src), "r"((uint32_t)(bytes)),  \
                    "r"((uint32_t)(mbar)) : "memory")

// ---------------------------------------------------------------------------
// Router: logits[n][e] = dot(x[n], gate_w[e]); one warp per token (fp32 exact)
// ---------------------------------------------------------------------------
__global__ void router_kernel(const float* __restrict__ x,
                              const float* __restrict__ gw) {
    int warp = threadIdx.x >> 5;
    int lane = threadIdx.x & 31;
    int n = blockIdx.x * 8 + warp;
    if (n >= NTOK) return;

    const float4* xr = (const float4*)(x + (size_t)n * DDIM);
    float acc[ENUM];
#pragma unroll
    for (int e = 0; e < ENUM; e++) acc[e] = 0.0f;

    for (int i = lane; i < DDIM / 4; i += 32) {
        float4 xv = xr[i];
#pragma unroll
        for (int e = 0; e < ENUM; e++) {
            float4 gv = ((const float4*)(gw + (size_t)e * DDIM))[i];
            acc[e] += xv.x * gv.x + xv.y * gv.y + xv.z * gv.z + xv.w * gv.w;
        }
    }
#pragma unroll
    for (int e = 0; e < ENUM; e++) {
#pragma unroll
        for (int off = 16; off > 0; off >>= 1)
            acc[e] += __shfl_down_sync(0xFFFFFFFFu, acc[e], off);
    }
    if (lane == 0) {
#pragma unroll
        for (int e = 0; e < ENUM; e++)
            g_logits[(size_t)n * ENUM + e] = acc[e];
    }
}

// Deterministic per-expert column sum (fixed partition + fixed tree)
__global__ void colsum_kernel() {
    __shared__ float s[256];
    int e = blockIdx.x;
    float a = 0.0f;
    for (int n = threadIdx.x; n < NTOK; n += 256)
        a += g_logits[(size_t)n * ENUM + e];
    s[threadIdx.x] = a;
    __syncthreads();
    for (int stride = 128; stride > 0; stride >>= 1) {
        if (threadIdx.x < stride) s[threadIdx.x] += s[threadIdx.x + stride];
        __syncthreads();
    }
    if (threadIdx.x == 0) g_sums[e] = s[0];
}

// Top-2 select (stable descending: ties -> lower index, matches lax.top_k)
__global__ void select_kernel() {
    if (threadIdx.x != 0 || blockIdx.x != 0) return;
    float v0 = -INFINITY, v1 = -INFINITY;
    int b0 = 0, b1 = 0;
    for (int e = 0; e < ENUM; e++) {
        float v = g_sums[e];
        if (v > v0) { v1 = v0; b1 = b0; v0 = v; b0 = e; }
        else if (v > v1) { v1 = v; b1 = e; }
    }
    g_sel[0] = b0;
    g_sel[1] = b1;
}

// Per-token softmax over the two selected experts' logits
__global__ void rw_kernel() {
    int n = blockIdx.x * blockDim.x + threadIdx.x;
    if (n >= NTOK) return;
    int s0 = g_sel[0], s1 = g_sel[1];
    float l0 = g_logits[(size_t)n * ENUM + s0];
    float l1 = g_logits[(size_t)n * ENUM + s1];
    float m = fmaxf(l0, l1);
    float e0 = expf(l0 - m);
    float e1 = expf(l1 - m);
    float inv = 1.0f / (e0 + e1);
    g_rw[2 * n + 0] = e0 * inv;
    g_rw[2 * n + 1] = e1 * inv;
}

// ---------------------------------------------------------------------------
// tf32 rounding pre-passes (round-to-nearest; avoids HW truncation bias)
// ---------------------------------------------------------------------------
__global__ void round_copy(const float* __restrict__ src, float* __restrict__ dst,
                           int n4) {
    int i = blockIdx.x * blockDim.x + threadIdx.x;
    if (i >= n4) return;
    float4 v = ((const float4*)src)[i];
    v.x = to_tf32(v.x); v.y = to_tf32(v.y);
    v.z = to_tf32(v.z); v.w = to_tf32(v.w);
    ((float4*)dst)[i] = v;
}

// Gathers the selected expert's slice (sel read on device) + rounds to tf32.
__global__ void round_expert(const float* __restrict__ base, float* __restrict__ dst,
                             size_t per_expert, int kslot, int n4) {
    int i = blockIdx.x * blockDim.x + threadIdx.x;
    if (i >= n4) return;
    const float4* src = (const float4*)(base + (size_t)g_sel[kslot] * per_expert);
    float4 v = src[i];
    v.x = to_tf32(v.x); v.y = to_tf32(v.y);
    v.z = to_tf32(v.z); v.w = to_tf32(v.w);
    ((float4*)dst)[i] = v;
}

// ---------------------------------------------------------------------------
// tf32 tensor-core GEMM: 256x128x32 block tile, 8 warps (4x2), warp 64x64,
// m16n8k8 frags (4x8 per warp), 3-stage pipeline filled by cp.async.bulk
// row-copies (one bulk op per smem row) with mbarrier tx-completion.
//   C = A[M,K] @ B[K,N]   (A,B pre-rounded to tf32)
// MODE 0 (GEMM1): C[r, c] = to_tf32( rw[r][kslot] * gelu(acc + b1[sel][c]) )
//                 C pre-offset to h + kslot*FDIM, ldc = 2*FDIM
// MODE 1 (GEMM2): C[r, c] = acc + rw[r][0]*b2[s0][c] + rw[r][1]*b2[s1][c]
// ---------------------------------------------------------------------------
#define BM 256
#define BN 128
#define BKT 32
#define SA 36                       // As[m][k] stride (floats) = 144B (16B multiple)
#define SB 136                      // Bs[k][n] stride (floats) = 544B (16B multiple)
#define ASZ (BM * SA)               // 9216 floats / stage
#define BSZ (BKT * SB)              // 4352 floats / stage
#define STAGES 3
#define GEMM_SMEM ((ASZ + BSZ) * STAGES * 4)   // 162816 bytes
#define TXB (BM * BKT * 4 + BKT * BN * 4)      // 49152 bytes per stage

template <int MODE>
__global__ void __launch_bounds__(256, 1)
gemm_tf32(const float* __restrict__ A, const float* __restrict__ B,
          const float* __restrict__ b1v, const float* __restrict__ b2v,
          float* __restrict__ C, int N, int K, int ldc, int kslot) {
    extern __shared__ float smem[];
    __shared__ __align__(8) uint64_t mb_store[STAGES];

    const int tid = threadIdx.x;
    const int lane = tid & 31;
    const int warp = tid >> 5;
    const int mW = (warp >> 1) * 64;   // 4 warp-rows
    const int nW = (warp & 1) * 64;    // 2 warp-cols

    uint32_t mb0;
    asm("{ .reg .u64 t; cvta.to.shared.u64 t, %1; cvt.u32.u64 %0, t; }"
        : "=r"(mb0) : "l"(mb_store));

    if (tid == 0) {
#pragma unroll
        for (int s = 0; s < STAGES; s++) MBINIT(mb0 + s * 8, 1);
    }
    __syncthreads();

    const float* Ap = A + (size_t)blockIdx.y * BM * K;
    const float* Bp = B + (size_t)blockIdx.x * BN;

    float acc[4][8][4];
#pragma unroll
    for (int mf = 0; mf < 4; mf++)
#pragma unroll
        for (int nf = 0; nf < 8; nf++)
#pragma unroll
            for (int i = 0; i < 4; i++) acc[mf][nf][i] = 0.0f;

    const int NT = K / BKT;

    // One bulk-copy per smem row: A rows (128B) by all 256 threads, B rows
    // (512B) by threads 0..31. tid 0 arms expect_tx (arrive count = 1).
    auto issue = [&](int kt) {
        const int buf = kt % STAGES;
        const uint32_t mb = mb0 + buf * 8;
        if (tid == 0) MBEXPECT(mb, TXB);
        float* Asm = smem + (size_t)buf * (ASZ + BSZ);
        float* Bsm = Asm + ASZ;
        {
            uint32_t d;
            const float* s = Ap + (size_t)tid * K + (size_t)kt * BKT;
            asm("{ .reg .u64 t; cvta.to.shared.u64 t, %1; cvt.u32.u64 %0, t; }"
                : "=r"(d) : "l"(Asm + tid * SA));
            BULK(d, s, BKT * 4, mb);
        }
        if (tid < BKT) {
            uint32_t d;
            const float* s = Bp + ((size_t)kt * BKT + tid) * N;
            asm("{ .reg .u64 t; cvta.to.shared.u64 t, %1; cvt.u32.u64 %0, t; }"
                : "=r"(d) : "l"(Bsm + tid * SB));
            BULK(d, s, BN * 4, mb);
        }
    };

    issue(0);
    issue(1);

#pragma unroll 1
    for (int kt = 0; kt < NT; kt++) {
        if (kt + 2 < NT) issue(kt + 2);
        MBWAIT(mb0 + (kt % STAGES) * 8, (kt / STAGES) & 1);

        const float* Asb = smem + (size_t)(kt % STAGES) * (ASZ + BSZ);
        const float* Bsb = Asb + ASZ;

#pragma unroll
        for (int ks = 0; ks < 4; ks++) {
            uint32_t af[4][4];
            uint32_t bf[8][2];
            const int arow = mW + (lane >> 2);
            const int acol = ks * 8 + (lane & 3);
#pragma unroll
            for (int mf = 0; mf < 4; mf++) {
                const float* p = Asb + (size_t)(arow + mf * 16) * SA + acol;
                af[mf][0] = __float_as_uint(p[0]);
                af[mf][1] = __float_as_uint(p[8 * SA]);
                af[mf][2] = __float_as_uint(p[4]);
                af[mf][3] = __float_as_uint(p[8 * SA + 4]);
            }
            const int brow = ks * 8 + (lane & 3);
            const int bcol = nW + (lane >> 2);
#pragma unroll
            for (int nf = 0; nf < 8; nf++) {
                const float* p = Bsb + (size_t)brow * SB + bcol + nf * 8;
                bf[nf][0] = __float_as_uint(p[0]);
                bf[nf][1] = __float_as_uint(p[4 * SB]);
            }
#pragma unroll
            for (int mf = 0; mf < 4; mf++)
#pragma unroll
                for (int nf = 0; nf < 8; nf++)
                    mma_tf32(acc[mf][nf], af[mf], bf[nf]);
        }
        __syncthreads();
    }

    // --- epilogue (float2 vectorized stores) ---
    const int s0 = g_sel[0], s1 = g_sel[1];
    const int bNoff = blockIdx.x * BN;
    const float* bias1 = (MODE == 0) ? (b1v + (size_t)g_sel[kslot] * FDIM) : nullptr;
#pragma unroll
    for (int mf = 0; mf < 4; mf++) {
        int r0 = blockIdx.y * BM + mW + mf * 16 + (lane >> 2);
        int r1 = r0 + 8;
        float rwA0, rwA1, rwB0, rwB1;
        if (MODE == 0) {
            rwA0 = g_rw[r0 * 2 + kslot];
            rwB0 = g_rw[r1 * 2 + kslot];
            rwA1 = rwB1 = 0.0f;
        } else {
            rwA0 = g_rw[r0 * 2 + 0]; rwA1 = g_rw[r0 * 2 + 1];
            rwB0 = g_rw[r1 * 2 + 0]; rwB1 = g_rw[r1 * 2 + 1];
        }
#pragma unroll
        for (int nf = 0; nf < 8; nf++) {
            int c0 = bNoff + nW + nf * 8 + (lane & 3) * 2;
            float2* p0 = (float2*)(C + (size_t)r0 * ldc + c0);
            float2* p1 = (float2*)(C + (size_t)r1 * ldc + c0);
            if (MODE == 0) {
                float2 bv = *(const float2*)(bias1 + c0);
                float2 o0, o1;
                o0.x = to_tf32(rwA0 * gelu_tanh(acc[mf][nf][0] + bv.x));
                o0.y = to_tf32(rwA0 * gelu_tanh(acc[mf][nf][1] + bv.y));
                o1.x = to_tf32(rwB0 * gelu_tanh(acc[mf][nf][2] + bv.x));
                o1.y = to_tf32(rwB0 * gelu_tanh(acc[mf][nf][3] + bv.y));
                *p0 = o0;
                *p1 = o1;
            } else {
                float2 ba = *(const float2*)(b2v + (size_t)s0 * DDIM + c0);
                float2 bb = *(const float2*)(b2v + (size_t)s1 * DDIM + c0);
                float2 o0, o1;
                o0.x = acc[mf][nf][0] + rwA0 * ba.x + rwA1 * bb.x;
                o0.y = acc[mf][nf][1] + rwA0 * ba.y + rwA1 * bb.y;
                o1.x = acc[mf][nf][2] + rwB0 * ba.x + rwB1 * bb.x;
                o1.y = acc[mf][nf][3] + rwB0 * ba.y + rwB1 * bb.y;
                *p0 = o0;
                *p1 = o1;
            }
        }
    }
}

// ---------------------------------------------------------------------------
// Launch
// ---------------------------------------------------------------------------
extern "C" void kernel_launch(void* const* d_in, const int* in_sizes, int n_in,
                              void* d_out, int out_size) {
    (void)in_sizes; (void)n_in; (void)out_size;
    const float* x  = (const float*)d_in[0];  // [2,4096,2048]
    const float* gw = (const float*)d_in[1];  // [8,2048]
    const float* w1 = (const float*)d_in[2];  // [8,2048,8192]
    const float* b1 = (const float*)d_in[3];  // [8,8192]
    const float* w2 = (const float*)d_in[4];  // [8,8192,2048]
    const float* b2 = (const float*)d_in[5];  // [8,2048]
    float* out = (float*)d_out;               // [2,4096,2048]

    void* p;
    cudaGetSymbolAddress(&p, g_h);   float* h   = (float*)p;
    cudaGetSymbolAddress(&p, g_xr);  float* xr  = (float*)p;
    cudaGetSymbolAddress(&p, g_w1r); float* w1r = (float*)p;
    cudaGetSymbolAddress(&p, g_w2r); float* w2r = (float*)p;

    cudaFuncSetAttribute(gemm_tf32<0>, cudaFuncAttributeMaxDynamicSharedMemorySize, GEMM_SMEM);
    cudaFuncSetAttribute(gemm_tf32<1>, cudaFuncAttributeMaxDynamicSharedMemorySize, GEMM_SMEM);

    // Routing (exact fp32)
    router_kernel<<<NTOK / 8, 256>>>(x, gw);
    colsum_kernel<<<ENUM, 256>>>();
    select_kernel<<<1, 1>>>();
    rw_kernel<<<NTOK / 256, 256>>>();

    // Round operands to tf32 (rna)
    const size_t perW = (size_t)DDIM * FDIM;
    const int n4x = NTOK * DDIM / 4;
    const int n4w = (int)(perW / 4);
    round_copy<<<(n4x + 255) / 256, 256>>>(x, xr, n4x);
    round_expert<<<(n4w + 255) / 256, 256>>>(w1, w1r,        perW, 0, n4w);
    round_expert<<<(n4w + 255) / 256, 256>>>(w1, w1r + perW, perW, 1, n4w);
    round_expert<<<(n4w + 255) / 256, 256>>>(w2, w2r,        perW, 0, n4w);
    round_expert<<<(n4w + 255) / 256, 256>>>(w2, w2r + perW, perW, 1, n4w);

    // GEMM1 (x2 experts): h[:, k*F : (k+1)*F] = to_tf32(rw[:,k] * gelu(x @ w1[sel_k] + b1[sel_k]))
    dim3 g1(FDIM / BN, NTOK / BM);
    gemm_tf32<0><<<g1, 256, GEMM_SMEM>>>(xr, w1r,        b1, nullptr, h,
                                         FDIM, DDIM, 2 * FDIM, 0);
    gemm_tf32<0><<<g1, 256, GEMM_SMEM>>>(xr, w1r + perW, b1, nullptr, h + FDIM,
                                         FDIM, DDIM, 2 * FDIM, 1);

    // GEMM2 (single fused K=16384): out = h @ [w2[s0]; w2[s1]] + rw0*b2[s0] + rw1*b2[s1]
    dim3 g2(DDIM / BN, NTOK / BM);
    gemm_tf32<1><<<g2, 256, GEMM_SMEM>>>(h, w2r, nullptr, b2, out,
                                         DDIM, 2 * FDIM, DDIM, 0);
}

// round 10
// speedup vs baseline: 1.4312x; 1.4312x over previous
#include <cuda_runtime.h>
#include <math.h>
#include <stdint.h>

// Problem constants (B=2, S=4096 -> N=8192 tokens)
#define NTOK 8192
#define DDIM 2048
#define ENUM 8
#define FDIM 8192

// ---------------------------------------------------------------------------
// Device scratch (no allocations allowed -> __device__ globals)
// ---------------------------------------------------------------------------
__device__ float g_logits[NTOK * ENUM];          // [N, E] router logits
__device__ float g_sums[ENUM];                   // per-expert logit sums
__device__ int   g_sel[2];                       // top-2 expert indices
__device__ float g_rw[NTOK * 2];                 // per-token softmax weights
__device__ float g_h[(size_t)NTOK * 2 * FDIM];   // [N, 2F]: rw-scaled hidden, tf32
__device__ float g_xr[(size_t)NTOK * DDIM];      // x rounded to tf32
__device__ float g_w1t[(size_t)2 * FDIM * DDIM]; // [slot][F][D] transposed tf32
__device__ float g_w2t[(size_t)DDIM * 2 * FDIM]; // [D][2F]      transposed tf32

// ---------------------------------------------------------------------------
// Helpers
// ---------------------------------------------------------------------------
__device__ __forceinline__ float to_tf32(float x) {
    uint32_t u;
    asm("cvt.rna.tf32.f32 %0, %1;" : "=r"(u) : "f"(x));
    return __uint_as_float(u);
}

__device__ __forceinline__ float gelu_tanh(float v) {
    const float c0 = 0.7978845608028654f;   // sqrt(2/pi)
    const float c1 = 0.044715f;
    float v3 = v * v * v;
    float t = tanhf(c0 * (v + c1 * v3));
    return 0.5f * v * (1.0f + t);
}

__device__ __forceinline__ void mma_tf32(float (&c)[4], const uint32_t (&a)[4],
                                         const uint32_t (&b)[2]) {
    asm volatile(
        "mma.sync.aligned.m16n8k8.row.col.f32.tf32.tf32.f32 "
        "{%0,%1,%2,%3}, {%4,%5,%6,%7}, {%8,%9}, {%0,%1,%2,%3};"
        : "+f"(c[0]), "+f"(c[1]), "+f"(c[2]), "+f"(c[3])
        : "r"(a[0]), "r"(a[1]), "r"(a[2]), "r"(a[3]), "r"(b[0]), "r"(b[1]));
}

#define LDSM4(r0, r1, r2, r3, a)                                             \
    asm volatile("ldmatrix.sync.aligned.m8n8.x4.shared.b16 {%0,%1,%2,%3}, [%4];" \
                 : "=r"(r0), "=r"(r1), "=r"(r2), "=r"(r3) : "r"(a))

// ---------------------------------------------------------------------------
// Router: logits[n][e] = dot(x[n], gate_w[e]); one warp per token (fp32 exact)
// ---------------------------------------------------------------------------
__global__ void router_kernel(const float* __restrict__ x,
                              const float* __restrict__ gw) {
    int warp = threadIdx.x >> 5;
    int lane = threadIdx.x & 31;
    int n = blockIdx.x * 8 + warp;
    if (n >= NTOK) return;

    const float4* xr = (const float4*)(x + (size_t)n * DDIM);
    float acc[ENUM];
#pragma unroll
    for (int e = 0; e < ENUM; e++) acc[e] = 0.0f;

    for (int i = lane; i < DDIM / 4; i += 32) {
        float4 xv = xr[i];
#pragma unroll
        for (int e = 0; e < ENUM; e++) {
            float4 gv = ((const float4*)(gw + (size_t)e * DDIM))[i];
            acc[e] += xv.x * gv.x + xv.y * gv.y + xv.z * gv.z + xv.w * gv.w;
        }
    }
#pragma unroll
    for (int e = 0; e < ENUM; e++) {
#pragma unroll
        for (int off = 16; off > 0; off >>= 1)
            acc[e] += __shfl_down_sync(0xFFFFFFFFu, acc[e], off);
    }
    if (lane == 0) {
#pragma unroll
        for (int e = 0; e < ENUM; e++)
            g_logits[(size_t)n * ENUM + e] = acc[e];
    }
}

// Fused per-expert column sum + top-2 select (deterministic fixed tree)
__global__ void colsum_select_kernel() {
    __shared__ float s[ENUM];
    int w = threadIdx.x >> 5;
    int lane = threadIdx.x & 31;
    float a = 0.0f;
    for (int n = lane; n < NTOK; n += 32)
        a += g_logits[(size_t)n * ENUM + w];
#pragma unroll
    for (int off = 16; off > 0; off >>= 1)
        a += __shfl_down_sync(0xFFFFFFFFu, a, off);
    if (lane == 0) s[w] = a;
    __syncthreads();
    if (threadIdx.x == 0) {
        float v0 = -INFINITY, v1 = -INFINITY;
        int b0 = 0, b1 = 0;
        for (int e = 0; e < ENUM; e++) {
            float v = s[e];
            if (v > v0) { v1 = v0; b1 = b0; v0 = v; b0 = e; }
            else if (v > v1) { v1 = v; b1 = e; }
        }
        g_sel[0] = b0;
        g_sel[1] = b1;
    }
}

// Per-token softmax over the two selected experts' logits
__global__ void rw_kernel() {
    int n = blockIdx.x * blockDim.x + threadIdx.x;
    if (n >= NTOK) return;
    int s0 = g_sel[0], s1 = g_sel[1];
    float l0 = g_logits[(size_t)n * ENUM + s0];
    float l1 = g_logits[(size_t)n * ENUM + s1];
    float m = fmaxf(l0, l1);
    float e0 = expf(l0 - m);
    float e1 = expf(l1 - m);
    float inv = 1.0f / (e0 + e1);
    g_rw[2 * n + 0] = e0 * inv;
    g_rw[2 * n + 1] = e1 * inv;
}

// ---------------------------------------------------------------------------
// Pre-passes: round x to tf32; transpose+round selected w1/w2 slices.
// ---------------------------------------------------------------------------
__global__ void round_copy(const float* __restrict__ src, float* __restrict__ dst,
                           int n4) {
    int i = blockIdx.x * blockDim.x + threadIdx.x;
    if (i >= n4) return;
    float4 v = ((const float4*)src)[i];
    v.x = to_tf32(v.x); v.y = to_tf32(v.y);
    v.z = to_tf32(v.z); v.w = to_tf32(v.w);
    ((float4*)dst)[i] = v;
}

// grid (256, 64, 4); z<2: w1[sel][d][f] -> w1t[slot][f][d]
//                    z>=2: w2[sel][f][d] -> w2t[d][slot*F + f]
__global__ void transpose_all(const float* __restrict__ w1,
                              const float* __restrict__ w2,
                              float* __restrict__ w1t, float* __restrict__ w2t) {
    __shared__ float t[32][33];
    const int z = blockIdx.z;
    const int slot = z & 1;
    const size_t perW = (size_t)DDIM * FDIM;
    const float* in;
    float* out;
    size_t inCols, outLd, outOff;
    int k0, n0;
    if (z < 2) {
        in = w1 + (size_t)g_sel[slot] * perW;
        inCols = FDIM;
        k0 = blockIdx.y * 32;       // d
        n0 = blockIdx.x * 32;       // f
        out = w1t + (size_t)slot * perW;
        outLd = DDIM;
        outOff = 0;
    } else {
        in = w2 + (size_t)g_sel[slot] * perW;
        inCols = DDIM;
        k0 = blockIdx.x * 32;       // f
        n0 = blockIdx.y * 32;       // d
        out = w2t;
        outLd = 2 * FDIM;
        outOff = (size_t)slot * FDIM;
    }
#pragma unroll
    for (int i = 0; i < 4; i++) {
        int k = k0 + threadIdx.y + i * 8;
        t[threadIdx.y + i * 8][threadIdx.x] = in[(size_t)k * inCols + n0 + threadIdx.x];
    }
    __syncthreads();
#pragma unroll
    for (int i = 0; i < 4; i++) {
        int n = n0 + threadIdx.y + i * 8;
        out[(size_t)n * outLd + outOff + k0 + threadIdx.x] =
            to_tf32(t[threadIdx.x][threadIdx.y + i * 8]);
    }
}

// ---------------------------------------------------------------------------
// tf32 tensor-core GEMM: 256x128x32 block tile, 8 warps (4x2), warp 64x64,
// m16n8k8 frags via ldmatrix.x4 (both operands K-contiguous in smem),
// 3-stage cp.async pipeline.
//   C = A[M,K] @ Bt[N,K]^T   (A row-major, Bt row-major N-by-K, tf32-rounded)
// MODE 0 (GEMM1): C[r, c] = to_tf32( rw[r][kslot] * gelu(acc + b1[sel][c]) )
// MODE 1 (GEMM2): C[r, c] = acc + rw[r][0]*b2[s0][c] + rw[r][1]*b2[s1][c]
// ---------------------------------------------------------------------------
#define BM 256
#define BN 128
#define BKT 32
#define SA 36                       // stride (floats): 144B -> LDSM conflict-free
#define ASZ (BM * SA)               // 9216 floats / stage
#define BSZ (BN * SA)               // 4608 floats / stage
#define STAGES 3
#define GEMM_SMEM ((ASZ + BSZ) * STAGES * 4)   // 165888 bytes

template <int MODE>
__global__ void __launch_bounds__(256, 1)
gemm_tf32(const float* __restrict__ A, const float* __restrict__ Bt,
          const float* __restrict__ b1v, const float* __restrict__ b2v,
          float* __restrict__ C, int N, int K, int ldc, int kslot) {
    extern __shared__ float smem[];

    const int tid = threadIdx.x;
    const int lane = tid & 31;
    const int warp = tid >> 5;
    const int mW = (warp >> 1) * 64;   // 4 warp-rows
    const int nW = (warp & 1) * 64;    // 2 warp-cols

    const float* Ap = A + (size_t)blockIdx.y * BM * K;
    const float* Bp = Bt + (size_t)blockIdx.x * BN * K;

    uint32_t sbase;
    asm("{ .reg .u64 t; cvta.to.shared.u64 t, %1; cvt.u32.u64 %0, t; }"
        : "=r"(sbase) : "l"(smem));

    float acc[4][8][4];
#pragma unroll
    for (int mf = 0; mf < 4; mf++)
#pragma unroll
        for (int nf = 0; nf < 8; nf++)
#pragma unroll
            for (int i = 0; i < 4; i++) acc[mf][nf][i] = 0.0f;

    const int NT = K / BKT;

    auto issue = [&](int kt) {
        int buf = kt % STAGES;
        float* Asm = smem + (size_t)buf * (ASZ + BSZ);
        float* Bsm = Asm + ASZ;
#pragma unroll
        for (int i = 0; i < 8; i++) {                    // A: 2048 x 16B
            int idx = tid + 256 * i;
            int m = idx >> 3, kq = (idx & 7) * 4;
            uint32_t d = (uint32_t)__cvta_generic_to_shared(Asm + m * SA + kq);
            asm volatile("cp.async.cg.shared.global [%0], [%1], 16;"
                         :: "r"(d), "l"(Ap + (size_t)m * K + kt * BKT + kq));
        }
#pragma unroll
        for (int i = 0; i < 4; i++) {                    // B: 1024 x 16B
            int idx = tid + 256 * i;
            int n = idx >> 3, kq = (idx & 7) * 4;
            uint32_t d = (uint32_t)__cvta_generic_to_shared(Bsm + n * SA + kq);
            asm volatile("cp.async.cg.shared.global [%0], [%1], 16;"
                         :: "r"(d), "l"(Bp + (size_t)n * K + kt * BKT + kq));
        }
        asm volatile("cp.async.commit_group;");
    };

    issue(0);
    if (NT > 1) issue(1);

    // ldmatrix per-thread row/col selectors (tile layout in comments above)
    const int aRow = mW + (lane & 15);
    const int aCol = (lane >> 4) * 4;
    const int bRow = nW + (lane >> 4) * 8 + (lane & 7);
    const int bCol = ((lane >> 3) & 1) * 4;

#pragma unroll 1
    for (int kt = 0; kt < NT; kt++) {
        if (kt + 2 < NT) {
            issue(kt + 2);
            asm volatile("cp.async.wait_group 2;" ::: "memory");
        } else if (kt + 1 < NT) {
            asm volatile("cp.async.wait_group 1;" ::: "memory");
        } else {
            asm volatile("cp.async.wait_group 0;" ::: "memory");
        }
        __syncthreads();

        const uint32_t AsbA = sbase + (uint32_t)((kt % STAGES) * (ASZ + BSZ) * 4);
        const uint32_t BsbA = AsbA + ASZ * 4;

#pragma unroll
        for (int ks = 0; ks < 4; ks++) {
            uint32_t af[4][4];
            uint32_t bf[8][2];
#pragma unroll
            for (int mf = 0; mf < 4; mf++)
                LDSM4(af[mf][0], af[mf][1], af[mf][2], af[mf][3],
                      AsbA + (uint32_t)(((aRow + mf * 16) * SA + ks * 8 + aCol) * 4));
#pragma unroll
            for (int np = 0; np < 4; np++)
                LDSM4(bf[2 * np][0], bf[2 * np][1], bf[2 * np + 1][0], bf[2 * np + 1][1],
                      BsbA + (uint32_t)(((bRow + np * 16) * SA + ks * 8 + bCol) * 4));
#pragma unroll
            for (int mf = 0; mf < 4; mf++)
#pragma unroll
                for (int nf = 0; nf < 8; nf++)
                    mma_tf32(acc[mf][nf], af[mf], bf[nf]);
        }
        __syncthreads();
    }

    // --- epilogue (float2 vectorized stores) ---
    const int s0 = g_sel[0], s1 = g_sel[1];
    const int bNoff = blockIdx.x * BN;
    const float* bias1 = (MODE == 0) ? (b1v + (size_t)g_sel[kslot] * FDIM) : nullptr;
#pragma unroll
    for (int mf = 0; mf < 4; mf++) {
        int r0 = blockIdx.y * BM + mW + mf * 16 + (lane >> 2);
        int r1 = r0 + 8;
        float rwA0, rwA1, rwB0, rwB1;
        if (MODE == 0) {
            rwA0 = g_rw[r0 * 2 + kslot];
            rwB0 = g_rw[r1 * 2 + kslot];
            rwA1 = rwB1 = 0.0f;
        } else {
            rwA0 = g_rw[r0 * 2 + 0]; rwA1 = g_rw[r0 * 2 + 1];
            rwB0 = g_rw[r1 * 2 + 0]; rwB1 = g_rw[r1 * 2 + 1];
        }
#pragma unroll
        for (int nf = 0; nf < 8; nf++) {
            int c0 = bNoff + nW + nf * 8 + (lane & 3) * 2;
            float2* p0 = (float2*)(C + (size_t)r0 * ldc + c0);
            float2* p1 = (float2*)(C + (size_t)r1 * ldc + c0);
            if (MODE == 0) {
                float2 bv = *(const float2*)(bias1 + c0);
                float2 o0, o1;
                o0.x = to_tf32(rwA0 * gelu_tanh(acc[mf][nf][0] + bv.x));
                o0.y = to_tf32(rwA0 * gelu_tanh(acc[mf][nf][1] + bv.y));
                o1.x = to_tf32(rwB0 * gelu_tanh(acc[mf][nf][2] + bv.x));
                o1.y = to_tf32(rwB0 * gelu_tanh(acc[mf][nf][3] + bv.y));
                *p0 = o0;
                *p1 = o1;
            } else {
                float2 ba = *(const float2*)(b2v + (size_t)s0 * DDIM + c0);
                float2 bb = *(const float2*)(b2v + (size_t)s1 * DDIM + c0);
                float2 o0, o1;
                o0.x = acc[mf][nf][0] + rwA0 * ba.x + rwA1 * bb.x;
                o0.y = acc[mf][nf][1] + rwA0 * ba.y + rwA1 * bb.y;
                o1.x = acc[mf][nf][2] + rwB0 * ba.x + rwB1 * bb.x;
                o1.y = acc[mf][nf][3] + rwB0 * ba.y + rwB1 * bb.y;
                *p0 = o0;
                *p1 = o1;
            }
        }
    }
}

// ---------------------------------------------------------------------------
// Launch
// ---------------------------------------------------------------------------
extern "C" void kernel_launch(void* const* d_in, const int* in_sizes, int n_in,
                              void* d_out, int out_size) {
    (void)in_sizes; (void)n_in; (void)out_size;
    const float* x  = (const float*)d_in[0];  // [2,4096,2048]
    const float* gw = (const float*)d_in[1];  // [8,2048]
    const float* w1 = (const float*)d_in[2];  // [8,2048,8192]
    const float* b1 = (const float*)d_in[3];  // [8,8192]
    const float* w2 = (const float*)d_in[4];  // [8,8192,2048]
    const float* b2 = (const float*)d_in[5];  // [8,2048]
    float* out = (float*)d_out;               // [2,4096,2048]

    void* p;
    cudaGetSymbolAddress(&p, g_h);   float* h   = (float*)p;
    cudaGetSymbolAddress(&p, g_xr);  float* xr  = (float*)p;
    cudaGetSymbolAddress(&p, g_w1t); float* w1t = (float*)p;
    cudaGetSymbolAddress(&p, g_w2t); float* w2t = (float*)p;

    cudaFuncSetAttribute(gemm_tf32<0>, cudaFuncAttributeMaxDynamicSharedMemorySize, GEMM_SMEM);
    cudaFuncSetAttribute(gemm_tf32<1>, cudaFuncAttributeMaxDynamicSharedMemorySize, GEMM_SMEM);

    // Routing (exact fp32)                                        launches 1-3
    router_kernel<<<NTOK / 8, 256>>>(x, gw);
    colsum_select_kernel<<<1, 256>>>();
    rw_kernel<<<NTOK / 256, 256>>>();

    // Pre-passes                                                  launches 4-5
    const size_t perW = (size_t)DDIM * FDIM;
    const int n4x = NTOK * DDIM / 4;
    round_copy<<<(n4x + 255) / 256, 256>>>(x, xr, n4x);
    transpose_all<<<dim3(256, 64, 4), dim3(32, 8)>>>(w1, w2, w1t, w2t);

    // GEMM1 (x2): h[:, k*F:(k+1)*F] = to_tf32(rw[:,k]*gelu(x @ w1[sel_k] + b1))
    // launch 6 is gemm_tf32<0> slot 0 -> captured by ncu (-s 5 -c 1)
    dim3 g1(FDIM / BN, NTOK / BM);
    gemm_tf32<0><<<g1, 256, GEMM_SMEM>>>(xr, w1t,        b1, nullptr, h,
                                         FDIM, DDIM, 2 * FDIM, 0);
    gemm_tf32<0><<<g1, 256, GEMM_SMEM>>>(xr, w1t + perW, b1, nullptr, h + FDIM,
                                         FDIM, DDIM, 2 * FDIM, 1);

    // GEMM2 (single fused K=16384): out = h @ w2t^T + rw0*b2[s0] + rw1*b2[s1]
    dim3 g2(DDIM / BN, NTOK / BM);
    gemm_tf32<1><<<g2, 256, GEMM_SMEM>>>(h, w2t, nullptr, b2, out,
                                         DDIM, 2 * FDIM, DDIM, 0);
}